// round 1
// baseline (speedup 1.0000x reference)
#include <cuda_runtime.h>
#include <math.h>

// ---------------- problem constants ----------------
#define TT       2048
#define BB       32
#define NTOK     (TT*BB)        // 65536
#define DM       512
#define NH       8
#define DH       64
#define DFF      2048
#define NCLS     64
#define EVAL     256
#define DPE      256

// ---------------- scratch buffers (device globals; no mallocs allowed) ----------------
__device__ float g_H[(size_t)NTOK * DM];
__device__ float g_Q[(size_t)NTOK * DM];
__device__ float g_K[(size_t)NTOK * DM];
__device__ float g_V[(size_t)NTOK * DM];
__device__ float g_A[(size_t)NTOK * DM];
__device__ float g_T[(size_t)NTOK * DM];
__device__ float g_F[(size_t)NTOK * DFF];
__device__ float g_Y[(size_t)NTOK * NCLS];

// ---------------- embed + positional encoding ----------------
// h0[t,b,0:256]   = E[x[t,b]]
// h0[t,b,256:512] = PE(t) with div_j = exp(2j * (-ln(10000)/256))
__global__ void embed_kernel(const int* __restrict__ x, const float* __restrict__ E,
                             float* __restrict__ H)
{
    int idx = blockIdx.x * 256 + threadIdx.x;   // over NTOK*DM = 33.5M
    int d = idx & (DM - 1);
    int n = idx >> 9;                            // n = t*B + b
    float v;
    if (d < EVAL) {
        int cls = x[n];
        v = E[cls * EVAL + d];
    } else {
        int p = d - EVAL;            // 0..255
        int j = p >> 1;              // 0..127
        const float c = (float)(-9.210340371976184 / 256.0);  // -ln(10000)/DPE
        float freq = expf((float)(2 * j) * c);
        float ang  = (float)(n >> 5) * freq;     // t = n / B
        v = (p & 1) ? cosf(ang) : sinf(ang);
    }
    H[idx] = v;
}

// ---------------- SGEMM: C = act(A[M,K] @ W[K,N] + bias[N]) ----------------
// BM=BN=128, BK=16, 8x8 per thread, 256 threads.
// ACT: 0 = none, 1 = phi (elu+1), 2 = relu
template<int ACT>
__global__ __launch_bounds__(256, 2)
void sgemm(const float* __restrict__ A, const float* __restrict__ W,
           const float* __restrict__ bias, float* __restrict__ C,
           int M, int N, int K)
{
    __shared__ float As[16][128];
    __shared__ float Bs[16][128];

    const int tid = threadIdx.x;
    const int bm = blockIdx.y, bn = blockIdx.x;

    const int arow = tid >> 1;            // 0..127
    const int acol = (tid & 1) << 3;      // 0 or 8
    const int brow = tid >> 4;            // 0..15
    const int bcol = (tid & 15) << 3;     // 0..120
    const int tx = tid & 15, ty = tid >> 4;

    const float* Ap = A + (size_t)(bm * 128 + arow) * K + acol;
    const int gnB = bn * 128 + bcol;

    float acc[8][8];
#pragma unroll
    for (int i = 0; i < 8; i++)
#pragma unroll
        for (int j = 0; j < 8; j++) acc[i][j] = 0.f;

    for (int k0 = 0; k0 < K; k0 += 16) {
        float4 a0 = *(const float4*)(Ap + k0);
        float4 a1 = *(const float4*)(Ap + k0 + 4);
        As[acol + 0][arow] = a0.x; As[acol + 1][arow] = a0.y;
        As[acol + 2][arow] = a0.z; As[acol + 3][arow] = a0.w;
        As[acol + 4][arow] = a1.x; As[acol + 5][arow] = a1.y;
        As[acol + 6][arow] = a1.z; As[acol + 7][arow] = a1.w;

        if (gnB < N) {
            const float* Wp_ = W + (size_t)(k0 + brow) * N + gnB;
            *(float4*)&Bs[brow][bcol]     = *(const float4*)(Wp_);
            *(float4*)&Bs[brow][bcol + 4] = *(const float4*)(Wp_ + 4);
        } else {
            float4 z = make_float4(0.f, 0.f, 0.f, 0.f);
            *(float4*)&Bs[brow][bcol]     = z;
            *(float4*)&Bs[brow][bcol + 4] = z;
        }
        __syncthreads();

#pragma unroll
        for (int kk = 0; kk < 16; kk++) {
            float a[8], b[8];
            *(float4*)&a[0] = *(const float4*)&As[kk][ty * 8];
            *(float4*)&a[4] = *(const float4*)&As[kk][ty * 8 + 4];
            *(float4*)&b[0] = *(const float4*)&Bs[kk][tx * 8];
            *(float4*)&b[4] = *(const float4*)&Bs[kk][tx * 8 + 4];
#pragma unroll
            for (int i = 0; i < 8; i++)
#pragma unroll
                for (int j = 0; j < 8; j++)
                    acc[i][j] = fmaf(a[i], b[j], acc[i][j]);
        }
        __syncthreads();
    }

    const int gm0 = bm * 128 + ty * 8;
    const int gn0 = bn * 128 + tx * 8;
#pragma unroll
    for (int i = 0; i < 8; i++) {
#pragma unroll
        for (int j = 0; j < 8; j++) {
            int gn = gn0 + j;
            if (gn < N) {
                float v = acc[i][j] + bias[gn];
                if (ACT == 1) v = (v > 0.f) ? (v + 1.f) : expf(v);
                if (ACT == 2) v = fmaxf(v, 0.f);
                C[(size_t)(gm0 + i) * N + gn] = v;
            }
        }
    }
}

// ---------------- causal linear-attention scan ----------------
// One block per (b,h); thread m owns state column S[:,m] (64 regs).
// Per step: S[d][m] += k[d]*v[m]; num_m = sum_d q[d]*S[d][m]; den = q . Z + eps
__global__ __launch_bounds__(64)
void scan_kernel(const float* __restrict__ Q, const float* __restrict__ K,
                 const float* __restrict__ V, float* __restrict__ A)
{
    const int bh = blockIdx.x;         // 0..255
    const int b  = bh >> 3, h = bh & 7;
    const int m  = threadIdx.x;        // 0..63

    __shared__ float q_sh[64], k_sh[64], z_sh[64];

    float S[64];
#pragma unroll
    for (int d = 0; d < 64; d++) S[d] = 0.f;
    z_sh[m] = 0.f;
    __syncthreads();

    const size_t base = (size_t)b * DM + h * 64 + m;
    for (int t = 0; t < TT; t++) {
        const size_t idx = (size_t)t * (BB * DM) + base;
        float qv = Q[idx], kv = K[idx], vv = V[idx];
        q_sh[m] = qv; k_sh[m] = kv; z_sh[m] += kv;
        __syncthreads();

        float n0 = 0.f, n1 = 0.f, n2 = 0.f, n3 = 0.f;
        float d0 = 0.f, d1 = 0.f, d2 = 0.f, d3 = 0.f;
#pragma unroll
        for (int d = 0; d < 64; d += 4) {
            float kk0 = k_sh[d],   kk1 = k_sh[d+1], kk2 = k_sh[d+2], kk3 = k_sh[d+3];
            float qq0 = q_sh[d],   qq1 = q_sh[d+1], qq2 = q_sh[d+2], qq3 = q_sh[d+3];
            S[d]   = fmaf(kk0, vv, S[d]);   n0 = fmaf(qq0, S[d],   n0);
            S[d+1] = fmaf(kk1, vv, S[d+1]); n1 = fmaf(qq1, S[d+1], n1);
            S[d+2] = fmaf(kk2, vv, S[d+2]); n2 = fmaf(qq2, S[d+2], n2);
            S[d+3] = fmaf(kk3, vv, S[d+3]); n3 = fmaf(qq3, S[d+3], n3);
            d0 = fmaf(qq0, z_sh[d],   d0);  d1 = fmaf(qq1, z_sh[d+1], d1);
            d2 = fmaf(qq2, z_sh[d+2], d2);  d3 = fmaf(qq3, z_sh[d+3], d3);
        }
        float num = (n0 + n1) + (n2 + n3);
        float den = (d0 + d1) + (d2 + d3) + 1e-6f;
        A[idx] = num / den;
        __syncthreads();
    }
}

// ---------------- fused residual + LayerNorm (in place on H) ----------------
// H[n,:] = LN(H[n,:] + R[n,:]) * g + b   over 512 dims; 128 threads/block
__global__ __launch_bounds__(128)
void add_ln_kernel(float* __restrict__ H, const float* __restrict__ R,
                   const float* __restrict__ g, const float* __restrict__ be)
{
    __shared__ float sh[4];
    const int n = blockIdx.x, tid = threadIdx.x;
    const size_t base = (size_t)n * DM;

    float x[4];
    float s = 0.f;
#pragma unroll
    for (int i = 0; i < 4; i++) {
        int d = tid + 128 * i;
        x[i] = H[base + d] + R[base + d];
        s += x[i];
    }
#pragma unroll
    for (int o = 16; o > 0; o >>= 1) s += __shfl_xor_sync(0xffffffffu, s, o);
    if ((tid & 31) == 0) sh[tid >> 5] = s;
    __syncthreads();
    float mean = (sh[0] + sh[1] + sh[2] + sh[3]) * (1.f / 512.f);
    __syncthreads();

    float vs = 0.f;
#pragma unroll
    for (int i = 0; i < 4; i++) { float dl = x[i] - mean; vs += dl * dl; }
#pragma unroll
    for (int o = 16; o > 0; o >>= 1) vs += __shfl_xor_sync(0xffffffffu, vs, o);
    if ((tid & 31) == 0) sh[tid >> 5] = vs;
    __syncthreads();
    float var = (sh[0] + sh[1] + sh[2] + sh[3]) * (1.f / 512.f);
    float inv = rsqrtf(var + 1e-5f);

#pragma unroll
    for (int i = 0; i < 4; i++) {
        int d = tid + 128 * i;
        H[base + d] = fmaf((x[i] - mean) * inv, g[d], be[d]);
    }
}

// ---------------- [T,B,C] -> [B,T,C] remap ----------------
__global__ void remap_kernel(const float* __restrict__ Y, float* __restrict__ out)
{
    int idx = blockIdx.x * 256 + threadIdx.x;   // out flat index: b*T*64 + t*64 + c
    int c = idx & 63;
    int t = (idx >> 6) & (TT - 1);
    int b = idx >> 17;
    out[idx] = Y[(size_t)(t * BB + b) * NCLS + c];
}

// ---------------- orchestration ----------------
extern "C" void kernel_launch(void* const* d_in, const int* in_sizes, int n_in,
                              void* d_out, int out_size)
{
    (void)in_sizes; (void)n_in; (void)out_size;
    const int*   x   = (const int*)d_in[0];
    const float* E   = (const float*)d_in[1];
    const float* Wq  = (const float*)d_in[2];  const float* bq  = (const float*)d_in[3];
    const float* Wk  = (const float*)d_in[4];  const float* bk  = (const float*)d_in[5];
    const float* Wv  = (const float*)d_in[6];  const float* bv  = (const float*)d_in[7];
    const float* Wo  = (const float*)d_in[8];  const float* bo  = (const float*)d_in[9];
    const float* g1  = (const float*)d_in[10]; const float* be1 = (const float*)d_in[11];
    const float* W1  = (const float*)d_in[12]; const float* b1  = (const float*)d_in[13];
    const float* W2  = (const float*)d_in[14]; const float* b2  = (const float*)d_in[15];
    const float* g2  = (const float*)d_in[16]; const float* be2 = (const float*)d_in[17];
    const float* Wp  = (const float*)d_in[18]; const float* bp  = (const float*)d_in[19];
    float* out = (float*)d_out;

    float *pH, *pQ, *pK, *pV, *pA, *pT, *pF, *pY;
    cudaGetSymbolAddress((void**)&pH, g_H);
    cudaGetSymbolAddress((void**)&pQ, g_Q);
    cudaGetSymbolAddress((void**)&pK, g_K);
    cudaGetSymbolAddress((void**)&pV, g_V);
    cudaGetSymbolAddress((void**)&pA, g_A);
    cudaGetSymbolAddress((void**)&pT, g_T);
    cudaGetSymbolAddress((void**)&pF, g_F);
    cudaGetSymbolAddress((void**)&pY, g_Y);

    embed_kernel<<<(NTOK * DM) / 256, 256>>>(x, E, pH);

    const dim3 gDM(DM / 128, NTOK / 128);     // (4, 512)
    const dim3 gFF(DFF / 128, NTOK / 128);    // (16, 512)
    const dim3 gP(1, NTOK / 128);             // (1, 512)

    for (int l = 0; l < 2; l++) {
        const size_t wOff  = (size_t)l * DM * DM;
        const size_t bOff  = (size_t)l * DM;
        const size_t w1Off = (size_t)l * DM * DFF;
        const size_t b1Off = (size_t)l * DFF;
        const size_t w2Off = (size_t)l * DFF * DM;

        sgemm<1><<<gDM, 256>>>(pH, Wq + wOff, bq + bOff, pQ, NTOK, DM, DM);
        sgemm<1><<<gDM, 256>>>(pH, Wk + wOff, bk + bOff, pK, NTOK, DM, DM);
        sgemm<0><<<gDM, 256>>>(pH, Wv + wOff, bv + bOff, pV, NTOK, DM, DM);

        scan_kernel<<<BB * NH, 64>>>(pQ, pK, pV, pA);

        sgemm<0><<<gDM, 256>>>(pA, Wo + wOff, bo + bOff, pT, NTOK, DM, DM);
        add_ln_kernel<<<NTOK, 128>>>(pH, pT, g1 + bOff, be1 + bOff);

        sgemm<2><<<gFF, 256>>>(pH, W1 + w1Off, b1 + b1Off, pF, NTOK, DFF, DM);
        sgemm<0><<<gDM, 256>>>(pF, W2 + w2Off, b2 + bOff, pT, NTOK, DM, DFF);
        add_ln_kernel<<<NTOK, 128>>>(pH, pT, g2 + bOff, be2 + bOff);
    }

    sgemm<0><<<gP, 256>>>(pH, Wp, bp, pY, NTOK, NCLS, DM);
    remap_kernel<<<(BB * TT * NCLS) / 256, 256>>>(pY, out);
}

// round 3
// speedup vs baseline: 4.9366x; 4.9366x over previous
#include <cuda_runtime.h>
#include <cuda_fp16.h>
#include <cstdint>
#include <math.h>

// ---------------- problem constants ----------------
#define TT       2048
#define BB       32
#define NTOK     (TT*BB)        // 65536
#define DM       512
#define NH       8
#define DH       64
#define DFF      2048
#define NCLS     64
#define EVAL     256
#define DPE      256
#define NLAYERS  2

// ---------------- scratch buffers (device globals; no mallocs allowed) ----------------
__device__ float  g_H[(size_t)NTOK * DM];
__device__ float  g_Q[(size_t)NTOK * DM];
__device__ float  g_K[(size_t)NTOK * DM];
__device__ float  g_V[(size_t)NTOK * DM];
__device__ float  g_T[(size_t)NTOK * DM];
__device__ float  g_Y[(size_t)NTOK * NCLS];
__device__ __half g_Hh[(size_t)NTOK * DM];
__device__ __half g_Ah[(size_t)NTOK * DM];
__device__ __half g_Fh[(size_t)NTOK * DFF];
__device__ __half g_Wqh[NLAYERS * DM * DM];
__device__ __half g_Wkh[NLAYERS * DM * DM];
__device__ __half g_Wvh[NLAYERS * DM * DM];
__device__ __half g_Woh[NLAYERS * DM * DM];
__device__ __half g_W1h[NLAYERS * DM * DFF];
__device__ __half g_W2h[NLAYERS * DFF * DM];
__device__ __half g_Wph[DM * NCLS];

// ---------------- fp32 -> fp16 conversion ----------------
__global__ void f2h_kernel(const float4* __restrict__ src, __half2* __restrict__ dst, int n4)
{
    int i = blockIdx.x * 256 + threadIdx.x;
    if (i < n4) {
        float4 v = src[i];
        dst[2 * i]     = __floats2half2_rn(v.x, v.y);
        dst[2 * i + 1] = __floats2half2_rn(v.z, v.w);
    }
}

// ---------------- embed + positional encoding (fp32 + fp16 copies) ----------------
__global__ void embed_kernel(const int* __restrict__ x, const float* __restrict__ E,
                             float* __restrict__ H, __half* __restrict__ Hh)
{
    int idx = blockIdx.x * 256 + threadIdx.x;
    int d = idx & (DM - 1);
    int n = idx >> 9;
    float v;
    if (d < EVAL) {
        int cls = x[n];
        v = E[cls * EVAL + d];
    } else {
        int p = d - EVAL;
        int j = p >> 1;
        const float c = (float)(-9.210340371976184 / 256.0);
        float freq = expf((float)(2 * j) * c);
        float ang  = (float)(n >> 5) * freq;
        v = (p & 1) ? cosf(ang) : sinf(ang);
    }
    H[idx] = v;
    Hh[idx] = __float2half_rn(v);
}

// ---------------- tensor-core HGEMM ----------------
__device__ __forceinline__ uint32_t smem_u32(const void* p) {
    return (uint32_t)__cvta_generic_to_shared(p);
}
__device__ __forceinline__ void ldsm_x4(uint32_t addr, uint32_t& r0, uint32_t& r1,
                                        uint32_t& r2, uint32_t& r3) {
    asm volatile("ldmatrix.sync.aligned.m8n8.x4.shared.b16 {%0,%1,%2,%3},[%4];\n"
                 : "=r"(r0), "=r"(r1), "=r"(r2), "=r"(r3) : "r"(addr));
}
__device__ __forceinline__ void ldsm_x4t(uint32_t addr, uint32_t& r0, uint32_t& r1,
                                         uint32_t& r2, uint32_t& r3) {
    asm volatile("ldmatrix.sync.aligned.m8n8.x4.trans.shared.b16 {%0,%1,%2,%3},[%4];\n"
                 : "=r"(r0), "=r"(r1), "=r"(r2), "=r"(r3) : "r"(addr));
}
__device__ __forceinline__ void mma16816(float* d, const uint32_t* a, uint32_t b0, uint32_t b1) {
    asm volatile("mma.sync.aligned.m16n8k16.row.col.f32.f16.f16.f32 "
                 "{%0,%1,%2,%3},{%4,%5,%6,%7},{%8,%9},{%0,%1,%2,%3};\n"
                 : "+f"(d[0]), "+f"(d[1]), "+f"(d[2]), "+f"(d[3])
                 : "r"(a[0]), "r"(a[1]), "r"(a[2]), "r"(a[3]), "r"(b0), "r"(b1));
}

template<int ACT>
__device__ __forceinline__ float act_apply(float v) {
    if (ACT == 1) return (v > 0.f) ? (v + 1.f) : expf(v);
    if (ACT == 2) return fmaxf(v, 0.f);
    return v;
}

// C = act(A[M,K]f16 @ W[K,N]f16 + bias); writes fp32 and/or fp16 outputs.
// BM=BN=128, BK=32, 8 warps (2x4), warp tile 64x32.
#define APITCH 40
#define BPITCH 136
template<int ACT, int WF32, int WF16>
__global__ __launch_bounds__(256, 2)
void hgemm(const __half* __restrict__ A, const __half* __restrict__ W,
           const float* __restrict__ bias, float* __restrict__ C32,
           __half* __restrict__ C16, int M, int N, int K)
{
    __shared__ __half As[128 * APITCH];
    __shared__ __half Bs[32 * BPITCH];

    const int tid = threadIdx.x;
    const int bm = blockIdx.y, bn = blockIdx.x;
    const int wid = tid >> 5, lane = tid & 31;
    const int wm = wid >> 2, wn = wid & 3;

    float acc[4][4][4];
#pragma unroll
    for (int i = 0; i < 4; i++)
#pragma unroll
        for (int j = 0; j < 4; j++)
#pragma unroll
            for (int r = 0; r < 4; r++) acc[i][j][r] = 0.f;

    const int aRow = tid >> 1, aCol = (tid & 1) * 16;
    const __half* Ag = A + (size_t)(bm * 128 + aRow) * K + aCol;
    const int bRow = tid >> 3, bCol = (tid & 7) * 16;
    const int gnB = bn * 128 + bCol;
    const __half* Wg = W + (size_t)bRow * N + gnB;

    const uint32_t aBase = smem_u32(As) + (uint32_t)((wm * 64 + (lane & 15)) * APITCH + (lane >> 4) * 8) * 2;
    const uint32_t bBase = smem_u32(Bs) + (uint32_t)((lane & 15) * BPITCH + wn * 32 + (lane >> 4) * 8) * 2;

    for (int k0 = 0; k0 < K; k0 += 32) {
        int4 av0 = *(const int4*)(Ag + k0);
        int4 av1 = *(const int4*)(Ag + k0 + 8);
        int4 bv0 = make_int4(0, 0, 0, 0), bv1 = make_int4(0, 0, 0, 0);
        if (gnB < N) {
            bv0 = *(const int4*)(Wg + (size_t)k0 * N);
            bv1 = *(const int4*)(Wg + (size_t)k0 * N + 8);
        }
        __syncthreads();
        *(int4*)&As[aRow * APITCH + aCol]     = av0;
        *(int4*)&As[aRow * APITCH + aCol + 8] = av1;
        *(int4*)&Bs[bRow * BPITCH + bCol]     = bv0;
        *(int4*)&Bs[bRow * BPITCH + bCol + 8] = bv1;
        __syncthreads();

#pragma unroll
        for (int ks = 0; ks < 2; ks++) {
            uint32_t a[4][4], b[2][4];
#pragma unroll
            for (int mt = 0; mt < 4; mt++)
                ldsm_x4(aBase + (uint32_t)(mt * 16 * APITCH + ks * 16) * 2,
                        a[mt][0], a[mt][1], a[mt][2], a[mt][3]);
#pragma unroll
            for (int nt = 0; nt < 2; nt++)
                ldsm_x4t(bBase + (uint32_t)(ks * 16 * BPITCH + nt * 16) * 2,
                         b[nt][0], b[nt][1], b[nt][2], b[nt][3]);
#pragma unroll
            for (int mt = 0; mt < 4; mt++) {
#pragma unroll
                for (int nt = 0; nt < 2; nt++) {
                    mma16816(acc[mt][nt * 2],     a[mt], b[nt][0], b[nt][1]);
                    mma16816(acc[mt][nt * 2 + 1], a[mt], b[nt][2], b[nt][3]);
                }
            }
        }
    }

    const int gr = lane >> 2, tg = lane & 3;
#pragma unroll
    for (int mt = 0; mt < 4; mt++) {
        const int gm0 = bm * 128 + wm * 64 + mt * 16 + gr;
#pragma unroll
        for (int n8 = 0; n8 < 4; n8++) {
            const int gn = bn * 128 + wn * 32 + n8 * 8 + tg * 2;
            if (gn < N) {
                float b0 = bias[gn], b1 = bias[gn + 1];
                float* ac = acc[mt][n8];
                float v00 = act_apply<ACT>(ac[0] + b0);
                float v01 = act_apply<ACT>(ac[1] + b1);
                float v10 = act_apply<ACT>(ac[2] + b0);
                float v11 = act_apply<ACT>(ac[3] + b1);
                if (WF32) {
                    C32[(size_t)gm0 * N + gn]           = v00;
                    C32[(size_t)gm0 * N + gn + 1]       = v01;
                    C32[(size_t)(gm0 + 8) * N + gn]     = v10;
                    C32[(size_t)(gm0 + 8) * N + gn + 1] = v11;
                }
                if (WF16) {
                    *(__half2*)&C16[(size_t)gm0 * N + gn]       = __floats2half2_rn(v00, v01);
                    *(__half2*)&C16[(size_t)(gm0 + 8) * N + gn] = __floats2half2_rn(v10, v11);
                }
            }
        }
    }
}

// ---------------- causal linear-attention scan (writes fp16 A) ----------------
__global__ __launch_bounds__(64)
void scan_kernel(const float* __restrict__ Q, const float* __restrict__ K,
                 const float* __restrict__ V, __half* __restrict__ A)
{
    const int bh = blockIdx.x;
    const int b  = bh >> 3, h = bh & 7;
    const int m  = threadIdx.x;

    __shared__ float q_sh[64], k_sh[64], z_sh[64];

    float S[64];
#pragma unroll
    for (int d = 0; d < 64; d++) S[d] = 0.f;
    z_sh[m] = 0.f;
    __syncthreads();

    const size_t base = (size_t)b * DM + h * 64 + m;
    for (int t = 0; t < TT; t++) {
        const size_t idx = (size_t)t * (BB * DM) + base;
        float qv = Q[idx], kv = K[idx], vv = V[idx];
        q_sh[m] = qv; k_sh[m] = kv; z_sh[m] += kv;
        __syncthreads();

        float n0 = 0.f, n1 = 0.f, n2 = 0.f, n3 = 0.f;
        float d0 = 0.f, d1 = 0.f, d2 = 0.f, d3 = 0.f;
#pragma unroll
        for (int d = 0; d < 64; d += 4) {
            float kk0 = k_sh[d],   kk1 = k_sh[d+1], kk2 = k_sh[d+2], kk3 = k_sh[d+3];
            float qq0 = q_sh[d],   qq1 = q_sh[d+1], qq2 = q_sh[d+2], qq3 = q_sh[d+3];
            S[d]   = fmaf(kk0, vv, S[d]);   n0 = fmaf(qq0, S[d],   n0);
            S[d+1] = fmaf(kk1, vv, S[d+1]); n1 = fmaf(qq1, S[d+1], n1);
            S[d+2] = fmaf(kk2, vv, S[d+2]); n2 = fmaf(qq2, S[d+2], n2);
            S[d+3] = fmaf(kk3, vv, S[d+3]); n3 = fmaf(qq3, S[d+3], n3);
            d0 = fmaf(qq0, z_sh[d],   d0);  d1 = fmaf(qq1, z_sh[d+1], d1);
            d2 = fmaf(qq2, z_sh[d+2], d2);  d3 = fmaf(qq3, z_sh[d+3], d3);
        }
        float num = (n0 + n1) + (n2 + n3);
        float den = (d0 + d1) + (d2 + d3) + 1e-6f;
        A[idx] = __float2half_rn(num / den);
        __syncthreads();
    }
}

// ---------------- fused residual + LayerNorm (fp32 + fp16 copies) ----------------
__global__ __launch_bounds__(128)
void add_ln_kernel(float* __restrict__ H, __half* __restrict__ Hh,
                   const float* __restrict__ R,
                   const float* __restrict__ g, const float* __restrict__ be)
{
    __shared__ float sh[4];
    const int n = blockIdx.x, tid = threadIdx.x;
    const size_t base = (size_t)n * DM;

    float x[4];
    float s = 0.f;
#pragma unroll
    for (int i = 0; i < 4; i++) {
        int d = tid + 128 * i;
        x[i] = H[base + d] + R[base + d];
        s += x[i];
    }
#pragma unroll
    for (int o = 16; o > 0; o >>= 1) s += __shfl_xor_sync(0xffffffffu, s, o);
    if ((tid & 31) == 0) sh[tid >> 5] = s;
    __syncthreads();
    float mean = (sh[0] + sh[1] + sh[2] + sh[3]) * (1.f / 512.f);
    __syncthreads();

    float vs = 0.f;
#pragma unroll
    for (int i = 0; i < 4; i++) { float dl = x[i] - mean; vs += dl * dl; }
#pragma unroll
    for (int o = 16; o > 0; o >>= 1) vs += __shfl_xor_sync(0xffffffffu, vs, o);
    if ((tid & 31) == 0) sh[tid >> 5] = vs;
    __syncthreads();
    float var = (sh[0] + sh[1] + sh[2] + sh[3]) * (1.f / 512.f);
    float inv = rsqrtf(var + 1e-5f);

#pragma unroll
    for (int i = 0; i < 4; i++) {
        int d = tid + 128 * i;
        float v = fmaf((x[i] - mean) * inv, g[d], be[d]);
        H[base + d] = v;
        Hh[base + d] = __float2half_rn(v);
    }
}

// ---------------- [T,B,C] -> [B,T,C] remap ----------------
__global__ void remap_kernel(const float* __restrict__ Y, float* __restrict__ out)
{
    int idx = blockIdx.x * 256 + threadIdx.x;
    int c = idx & 63;
    int t = (idx >> 6) & (TT - 1);
    int b = idx >> 17;
    out[idx] = Y[(size_t)(t * BB + b) * NCLS + c];
}

// ---------------- orchestration ----------------
static inline void conv_f2h(const float* src, __half* dst, int n)
{
    int n4 = n / 4;
    f2h_kernel<<<(n4 + 255) / 256, 256>>>((const float4*)src, (__half2*)dst, n4);
}

extern "C" void kernel_launch(void* const* d_in, const int* in_sizes, int n_in,
                              void* d_out, int out_size)
{
    (void)in_sizes; (void)n_in; (void)out_size;
    const int*   x   = (const int*)d_in[0];
    const float* E   = (const float*)d_in[1];
    const float* Wq  = (const float*)d_in[2];  const float* bq  = (const float*)d_in[3];
    const float* Wk  = (const float*)d_in[4];  const float* bk  = (const float*)d_in[5];
    const float* Wv  = (const float*)d_in[6];  const float* bv  = (const float*)d_in[7];
    const float* Wo  = (const float*)d_in[8];  const float* bo  = (const float*)d_in[9];
    const float* g1  = (const float*)d_in[10]; const float* be1 = (const float*)d_in[11];
    const float* W1  = (const float*)d_in[12]; const float* b1  = (const float*)d_in[13];
    const float* W2  = (const float*)d_in[14]; const float* b2  = (const float*)d_in[15];
    const float* g2  = (const float*)d_in[16]; const float* be2 = (const float*)d_in[17];
    const float* Wp  = (const float*)d_in[18]; const float* bp  = (const float*)d_in[19];
    float* out = (float*)d_out;

    float *pH, *pQ, *pK, *pV, *pT, *pY;
    __half *pHh, *pAh, *pFh, *pWqh, *pWkh, *pWvh, *pWoh, *pW1h, *pW2h, *pWph;
    cudaGetSymbolAddress((void**)&pH,  g_H);
    cudaGetSymbolAddress((void**)&pQ,  g_Q);
    cudaGetSymbolAddress((void**)&pK,  g_K);
    cudaGetSymbolAddress((void**)&pV,  g_V);
    cudaGetSymbolAddress((void**)&pT,  g_T);
    cudaGetSymbolAddress((void**)&pY,  g_Y);
    cudaGetSymbolAddress((void**)&pHh, g_Hh);
    cudaGetSymbolAddress((void**)&pAh, g_Ah);
    cudaGetSymbolAddress((void**)&pFh, g_Fh);
    cudaGetSymbolAddress((void**)&pWqh, g_Wqh);
    cudaGetSymbolAddress((void**)&pWkh, g_Wkh);
    cudaGetSymbolAddress((void**)&pWvh, g_Wvh);
    cudaGetSymbolAddress((void**)&pWoh, g_Woh);
    cudaGetSymbolAddress((void**)&pW1h, g_W1h);
    cudaGetSymbolAddress((void**)&pW2h, g_W2h);
    cudaGetSymbolAddress((void**)&pWph, g_Wph);

    // weight conversions (tiny)
    conv_f2h(Wq, pWqh, NLAYERS * DM * DM);
    conv_f2h(Wk, pWkh, NLAYERS * DM * DM);
    conv_f2h(Wv, pWvh, NLAYERS * DM * DM);
    conv_f2h(Wo, pWoh, NLAYERS * DM * DM);
    conv_f2h(W1, pW1h, NLAYERS * DM * DFF);
    conv_f2h(W2, pW2h, NLAYERS * DFF * DM);
    conv_f2h(Wp, pWph, DM * NCLS);

    embed_kernel<<<(NTOK * DM) / 256, 256>>>(x, E, pH, pHh);

    const dim3 gDM(DM / 128, NTOK / 128);     // (4, 512)
    const dim3 gFF(DFF / 128, NTOK / 128);    // (16, 512)
    const dim3 gP(1, NTOK / 128);             // (1, 512)

    for (int l = 0; l < NLAYERS; l++) {
        const size_t wOff  = (size_t)l * DM * DM;
        const size_t bOff  = (size_t)l * DM;
        const size_t w1Off = (size_t)l * DM * DFF;
        const size_t b1Off = (size_t)l * DFF;
        const size_t w2Off = (size_t)l * DFF * DM;

        hgemm<1,1,0><<<gDM, 256>>>(pHh, pWqh + wOff, bq + bOff, pQ, (__half*)0, NTOK, DM, DM);
        hgemm<1,1,0><<<gDM, 256>>>(pHh, pWkh + wOff, bk + bOff, pK, (__half*)0, NTOK, DM, DM);
        hgemm<0,1,0><<<gDM, 256>>>(pHh, pWvh + wOff, bv + bOff, pV, (__half*)0, NTOK, DM, DM);

        scan_kernel<<<BB * NH, 64>>>(pQ, pK, pV, pAh);

        hgemm<0,1,0><<<gDM, 256>>>(pAh, pWoh + wOff, bo + bOff, pT, (__half*)0, NTOK, DM, DM);
        add_ln_kernel<<<NTOK, 128>>>(pH, pHh, pT, g1 + bOff, be1 + bOff);

        hgemm<2,0,1><<<gFF, 256>>>(pHh, pW1h + w1Off, b1 + b1Off, (float*)0, pFh, NTOK, DFF, DM);
        hgemm<0,1,0><<<gDM, 256>>>(pFh, pW2h + w2Off, b2 + bOff, pT, (__half*)0, NTOK, DM, DFF);
        add_ln_kernel<<<NTOK, 128>>>(pH, pHh, pT, g2 + bOff, be2 + bOff);
    }

    hgemm<0,1,0><<<gP, 256>>>(pHh, pWph, bp, pY, (__half*)0, NTOK, NCLS, DM);
    remap_kernel<<<(BB * TT * NCLS) / 256, 256>>>(pY, out);
}

// round 5
// speedup vs baseline: 5.3088x; 1.0754x over previous
#include <cuda_runtime.h>
#include <cuda_fp16.h>
#include <cstdint>
#include <math.h>

// ---------------- problem constants ----------------
#define TT       2048
#define BB       32
#define NTOK     (TT*BB)        // 65536
#define DM       512
#define NH       8
#define DH       64
#define DFF      2048
#define NCLS     64
#define EVAL     256
#define DPE      256
#define NLAYERS  2

// ---------------- scratch buffers ----------------
__device__ float  g_H[(size_t)NTOK * DM];
__device__ float  g_Q[(size_t)NTOK * DM];
__device__ float  g_K[(size_t)NTOK * DM];
__device__ float  g_V[(size_t)NTOK * DM];
__device__ float  g_T[(size_t)NTOK * DM];
__device__ float  g_Y[(size_t)NTOK * NCLS];
__device__ __half g_Hh[(size_t)NTOK * DM];
__device__ __half g_Ah[(size_t)NTOK * DM];
__device__ __half g_Fh[(size_t)NTOK * DFF];
__device__ __half g_Wqh[NLAYERS * DM * DM];
__device__ __half g_Wkh[NLAYERS * DM * DM];
__device__ __half g_Wvh[NLAYERS * DM * DM];
__device__ __half g_Woh[NLAYERS * DM * DM];
__device__ __half g_W1h[NLAYERS * DM * DFF];
__device__ __half g_W2h[NLAYERS * DFF * DM];
__device__ __half g_Wph[DM * NCLS];

// ---------------- fp32 -> fp16 conversion ----------------
__global__ void f2h_kernel(const float4* __restrict__ src, __half2* __restrict__ dst, int n4)
{
    int i = blockIdx.x * 256 + threadIdx.x;
    if (i < n4) {
        float4 v = src[i];
        dst[2 * i]     = __floats2half2_rn(v.x, v.y);
        dst[2 * i + 1] = __floats2half2_rn(v.z, v.w);
    }
}

// ---------------- embed + positional encoding ----------------
__global__ void embed_kernel(const int* __restrict__ x, const float* __restrict__ E,
                             float* __restrict__ H, __half* __restrict__ Hh)
{
    int idx = blockIdx.x * 256 + threadIdx.x;
    int d = idx & (DM - 1);
    int n = idx >> 9;
    float v;
    if (d < EVAL) {
        int cls = x[n];
        v = E[cls * EVAL + d];
    } else {
        int p = d - EVAL;
        int j = p >> 1;
        const float c = (float)(-9.210340371976184 / 256.0);
        float freq = expf((float)(2 * j) * c);
        float ang  = (float)(n >> 5) * freq;
        v = (p & 1) ? cosf(ang) : sinf(ang);
    }
    H[idx] = v;
    Hh[idx] = __float2half_rn(v);
}

// ---------------- tensor-core HGEMM (3-stage cp.async pipeline) ----------------
__device__ __forceinline__ uint32_t smem_u32(const void* p) {
    return (uint32_t)__cvta_generic_to_shared(p);
}
__device__ __forceinline__ void ldsm_x4(uint32_t addr, uint32_t& r0, uint32_t& r1,
                                        uint32_t& r2, uint32_t& r3) {
    asm volatile("ldmatrix.sync.aligned.m8n8.x4.shared.b16 {%0,%1,%2,%3},[%4];\n"
                 : "=r"(r0), "=r"(r1), "=r"(r2), "=r"(r3) : "r"(addr));
}
__device__ __forceinline__ void ldsm_x4t(uint32_t addr, uint32_t& r0, uint32_t& r1,
                                         uint32_t& r2, uint32_t& r3) {
    asm volatile("ldmatrix.sync.aligned.m8n8.x4.trans.shared.b16 {%0,%1,%2,%3},[%4];\n"
                 : "=r"(r0), "=r"(r1), "=r"(r2), "=r"(r3) : "r"(addr));
}
__device__ __forceinline__ void mma16816(float* d, const uint32_t* a, uint32_t b0, uint32_t b1) {
    asm volatile("mma.sync.aligned.m16n8k16.row.col.f32.f16.f16.f32 "
                 "{%0,%1,%2,%3},{%4,%5,%6,%7},{%8,%9},{%0,%1,%2,%3};\n"
                 : "+f"(d[0]), "+f"(d[1]), "+f"(d[2]), "+f"(d[3])
                 : "r"(a[0]), "r"(a[1]), "r"(a[2]), "r"(a[3]), "r"(b0), "r"(b1));
}
__device__ __forceinline__ void cpa16(uint32_t dst, const void* src, int srcBytes) {
    asm volatile("cp.async.cg.shared.global [%0], [%1], 16, %2;\n"
                 :: "r"(dst), "l"(src), "r"(srcBytes));
}
__device__ __forceinline__ void cp_commit() {
    asm volatile("cp.async.commit_group;\n");
}
__device__ __forceinline__ void cp_wait1() {
    asm volatile("cp.async.wait_group 1;\n");
}

template<int ACT>
__device__ __forceinline__ float act_apply(float v) {
    if (ACT == 1) return (v > 0.f) ? (v + 1.f) : expf(v);
    if (ACT == 2) return fmaxf(v, 0.f);
    return v;
}

#define APITCH 40
#define BPITCH 136
#define STAGES 3

template<int ACT, int WF32, int WF16>
__global__ __launch_bounds__(256, 2)
void hgemm(const __half* __restrict__ A, const __half* __restrict__ W,
           const float* __restrict__ bias, float* __restrict__ C32,
           __half* __restrict__ C16, int M, int N, int K)
{
    __shared__ __half As[STAGES][128 * APITCH];
    __shared__ __half Bs[STAGES][32 * BPITCH];

    const int tid = threadIdx.x;
    const int bm = blockIdx.y, bn = blockIdx.x;
    const int wid = tid >> 5, lane = tid & 31;
    const int wm = wid >> 2, wn = wid & 3;

    float acc[4][4][4];
#pragma unroll
    for (int i = 0; i < 4; i++)
#pragma unroll
        for (int j = 0; j < 4; j++)
#pragma unroll
            for (int r = 0; r < 4; r++) acc[i][j][r] = 0.f;

    const int aRow = tid >> 1, aCol = (tid & 1) * 16;
    const __half* Ag = A + (size_t)(bm * 128 + aRow) * K + aCol;
    const int bRow = tid >> 3, bCol = (tid & 7) * 16;
    const int gnB = bn * 128 + bCol;
    const __half* Wg = W + (size_t)bRow * N + gnB;
    const int bPred = (gnB < N) ? 16 : 0;

    const uint32_t aDst0 = smem_u32(&As[0][aRow * APITCH + aCol]);
    const uint32_t bDst0 = smem_u32(&Bs[0][bRow * BPITCH + bCol]);
    const uint32_t aStg = 128 * APITCH * 2;   // bytes per A stage
    const uint32_t bStg = 32 * BPITCH * 2;    // bytes per B stage

    const int ktiles = K >> 5;

    // NOTE: +8 halves == +16 BYTES in smem (round-4 bug was +32).
#define LOAD_STAGE(kt, s)                                                     \
    do {                                                                      \
        const __half* ag_ = Ag + ((kt) << 5);                                 \
        cpa16(aDst0 + (s) * aStg,      ag_,     16);                          \
        cpa16(aDst0 + (s) * aStg + 16, ag_ + 8, 16);                          \
        const __half* wg_ = Wg + (size_t)((kt) << 5) * N;                     \
        cpa16(bDst0 + (s) * bStg,      wg_,     bPred);                       \
        cpa16(bDst0 + (s) * bStg + 16, wg_ + 8, bPred);                       \
    } while (0)

    LOAD_STAGE(0, 0); cp_commit();
    LOAD_STAGE(1, 1); cp_commit();

    const uint32_t aBase = smem_u32(As) + (uint32_t)((wm * 64 + (lane & 15)) * APITCH + (lane >> 4) * 8) * 2;
    const uint32_t bBase = smem_u32(Bs) + (uint32_t)((lane & 15) * BPITCH + wn * 32 + (lane >> 4) * 8) * 2;

    int s = 0;
    for (int kt = 0; kt < ktiles; kt++) {
        cp_wait1();
        __syncthreads();

        if (kt + 2 < ktiles) {
            int sn = (s + 2 >= STAGES) ? (s + 2 - STAGES) : (s + 2);
            LOAD_STAGE(kt + 2, sn);
        }
        cp_commit();

        const uint32_t aS = aBase + s * aStg;
        const uint32_t bS = bBase + s * bStg;
#pragma unroll
        for (int ks = 0; ks < 2; ks++) {
            uint32_t a[4][4], b[2][4];
#pragma unroll
            for (int mt = 0; mt < 4; mt++)
                ldsm_x4(aS + (uint32_t)(mt * 16 * APITCH + ks * 16) * 2,
                        a[mt][0], a[mt][1], a[mt][2], a[mt][3]);
#pragma unroll
            for (int nt = 0; nt < 2; nt++)
                ldsm_x4t(bS + (uint32_t)(ks * 16 * BPITCH + nt * 16) * 2,
                         b[nt][0], b[nt][1], b[nt][2], b[nt][3]);
#pragma unroll
            for (int mt = 0; mt < 4; mt++) {
#pragma unroll
                for (int nt = 0; nt < 2; nt++) {
                    mma16816(acc[mt][nt * 2],     a[mt], b[nt][0], b[nt][1]);
                    mma16816(acc[mt][nt * 2 + 1], a[mt], b[nt][2], b[nt][3]);
                }
            }
        }
        s = (s + 1 >= STAGES) ? 0 : (s + 1);
    }
#undef LOAD_STAGE

    const int gr = lane >> 2, tg = lane & 3;
#pragma unroll
    for (int mt = 0; mt < 4; mt++) {
        const int gm0 = bm * 128 + wm * 64 + mt * 16 + gr;
#pragma unroll
        for (int n8 = 0; n8 < 4; n8++) {
            const int gn = bn * 128 + wn * 32 + n8 * 8 + tg * 2;
            if (gn < N) {
                float b0 = bias[gn], b1 = bias[gn + 1];
                float* ac = acc[mt][n8];
                float v00 = act_apply<ACT>(ac[0] + b0);
                float v01 = act_apply<ACT>(ac[1] + b1);
                float v10 = act_apply<ACT>(ac[2] + b0);
                float v11 = act_apply<ACT>(ac[3] + b1);
                if (WF32) {
                    C32[(size_t)gm0 * N + gn]           = v00;
                    C32[(size_t)gm0 * N + gn + 1]       = v01;
                    C32[(size_t)(gm0 + 8) * N + gn]     = v10;
                    C32[(size_t)(gm0 + 8) * N + gn + 1] = v11;
                }
                if (WF16) {
                    *(__half2*)&C16[(size_t)gm0 * N + gn]       = __floats2half2_rn(v00, v01);
                    *(__half2*)&C16[(size_t)(gm0 + 8) * N + gn] = __floats2half2_rn(v10, v11);
                }
            }
        }
    }
}

// ---------------- causal linear-attention scan (writes fp16 A) ----------------
__global__ __launch_bounds__(64)
void scan_kernel(const float* __restrict__ Q, const float* __restrict__ K,
                 const float* __restrict__ V, __half* __restrict__ A)
{
    const int bh = blockIdx.x;
    const int b  = bh >> 3, h = bh & 7;
    const int m  = threadIdx.x;

    __shared__ float q_sh[64], k_sh[64], z_sh[64];

    float S[64];
#pragma unroll
    for (int d = 0; d < 64; d++) S[d] = 0.f;
    z_sh[m] = 0.f;
    __syncthreads();

    const size_t base = (size_t)b * DM + h * 64 + m;
    for (int t = 0; t < TT; t++) {
        const size_t idx = (size_t)t * (BB * DM) + base;
        float qv = Q[idx], kv = K[idx], vv = V[idx];
        q_sh[m] = qv; k_sh[m] = kv; z_sh[m] += kv;
        __syncthreads();

        float n0 = 0.f, n1 = 0.f, n2 = 0.f, n3 = 0.f;
        float d0 = 0.f, d1 = 0.f, d2 = 0.f, d3 = 0.f;
#pragma unroll
        for (int d = 0; d < 64; d += 4) {
            float kk0 = k_sh[d],   kk1 = k_sh[d+1], kk2 = k_sh[d+2], kk3 = k_sh[d+3];
            float qq0 = q_sh[d],   qq1 = q_sh[d+1], qq2 = q_sh[d+2], qq3 = q_sh[d+3];
            S[d]   = fmaf(kk0, vv, S[d]);   n0 = fmaf(qq0, S[d],   n0);
            S[d+1] = fmaf(kk1, vv, S[d+1]); n1 = fmaf(qq1, S[d+1], n1);
            S[d+2] = fmaf(kk2, vv, S[d+2]); n2 = fmaf(qq2, S[d+2], n2);
            S[d+3] = fmaf(kk3, vv, S[d+3]); n3 = fmaf(qq3, S[d+3], n3);
            d0 = fmaf(qq0, z_sh[d],   d0);  d1 = fmaf(qq1, z_sh[d+1], d1);
            d2 = fmaf(qq2, z_sh[d+2], d2);  d3 = fmaf(qq3, z_sh[d+3], d3);
        }
        float num = (n0 + n1) + (n2 + n3);
        float den = (d0 + d1) + (d2 + d3) + 1e-6f;
        A[idx] = __float2half_rn(num / den);
        __syncthreads();
    }
}

// ---------------- fused residual + LayerNorm ----------------
__global__ __launch_bounds__(128)
void add_ln_kernel(float* __restrict__ H, __half* __restrict__ Hh,
                   const float* __restrict__ R,
                   const float* __restrict__ g, const float* __restrict__ be)
{
    __shared__ float sh[4];
    const int n = blockIdx.x, tid = threadIdx.x;
    const size_t base = (size_t)n * DM;

    float x[4];
    float s = 0.f;
#pragma unroll
    for (int i = 0; i < 4; i++) {
        int d = tid + 128 * i;
        x[i] = H[base + d] + R[base + d];
        s += x[i];
    }
#pragma unroll
    for (int o = 16; o > 0; o >>= 1) s += __shfl_xor_sync(0xffffffffu, s, o);
    if ((tid & 31) == 0) sh[tid >> 5] = s;
    __syncthreads();
    float mean = (sh[0] + sh[1] + sh[2] + sh[3]) * (1.f / 512.f);
    __syncthreads();

    float vs = 0.f;
#pragma unroll
    for (int i = 0; i < 4; i++) { float dl = x[i] - mean; vs += dl * dl; }
#pragma unroll
    for (int o = 16; o > 0; o >>= 1) vs += __shfl_xor_sync(0xffffffffu, vs, o);
    if ((tid & 31) == 0) sh[tid >> 5] = vs;
    __syncthreads();
    float var = (sh[0] + sh[1] + sh[2] + sh[3]) * (1.f / 512.f);
    float inv = rsqrtf(var + 1e-5f);

#pragma unroll
    for (int i = 0; i < 4; i++) {
        int d = tid + 128 * i;
        float v = fmaf((x[i] - mean) * inv, g[d], be[d]);
        H[base + d] = v;
        Hh[base + d] = __float2half_rn(v);
    }
}

// ---------------- [T,B,C] -> [B,T,C] remap ----------------
__global__ void remap_kernel(const float* __restrict__ Y, float* __restrict__ out)
{
    int idx = blockIdx.x * 256 + threadIdx.x;
    int c = idx & 63;
    int t = (idx >> 6) & (TT - 1);
    int b = idx >> 17;
    out[idx] = Y[(size_t)(t * BB + b) * NCLS + c];
}

// ---------------- orchestration ----------------
static inline void conv_f2h(const float* src, __half* dst, int n)
{
    int n4 = n / 4;
    f2h_kernel<<<(n4 + 255) / 256, 256>>>((const float4*)src, (__half2*)dst, n4);
}

extern "C" void kernel_launch(void* const* d_in, const int* in_sizes, int n_in,
                              void* d_out, int out_size)
{
    (void)in_sizes; (void)n_in; (void)out_size;
    const int*   x   = (const int*)d_in[0];
    const float* E   = (const float*)d_in[1];
    const float* Wq  = (const float*)d_in[2];  const float* bq  = (const float*)d_in[3];
    const float* Wk  = (const float*)d_in[4];  const float* bk  = (const float*)d_in[5];
    const float* Wv  = (const float*)d_in[6];  const float* bv  = (const float*)d_in[7];
    const float* Wo  = (const float*)d_in[8];  const float* bo  = (const float*)d_in[9];
    const float* g1  = (const float*)d_in[10]; const float* be1 = (const float*)d_in[11];
    const float* W1  = (const float*)d_in[12]; const float* b1  = (const float*)d_in[13];
    const float* W2  = (const float*)d_in[14]; const float* b2  = (const float*)d_in[15];
    const float* g2  = (const float*)d_in[16]; const float* be2 = (const float*)d_in[17];
    const float* Wp  = (const float*)d_in[18]; const float* bp  = (const float*)d_in[19];
    float* out = (float*)d_out;

    float *pH, *pQ, *pK, *pV, *pT, *pY;
    __half *pHh, *pAh, *pFh, *pWqh, *pWkh, *pWvh, *pWoh, *pW1h, *pW2h, *pWph;
    cudaGetSymbolAddress((void**)&pH,  g_H);
    cudaGetSymbolAddress((void**)&pQ,  g_Q);
    cudaGetSymbolAddress((void**)&pK,  g_K);
    cudaGetSymbolAddress((void**)&pV,  g_V);
    cudaGetSymbolAddress((void**)&pT,  g_T);
    cudaGetSymbolAddress((void**)&pY,  g_Y);
    cudaGetSymbolAddress((void**)&pHh, g_Hh);
    cudaGetSymbolAddress((void**)&pAh, g_Ah);
    cudaGetSymbolAddress((void**)&pFh, g_Fh);
    cudaGetSymbolAddress((void**)&pWqh, g_Wqh);
    cudaGetSymbolAddress((void**)&pWkh, g_Wkh);
    cudaGetSymbolAddress((void**)&pWvh, g_Wvh);
    cudaGetSymbolAddress((void**)&pWoh, g_Woh);
    cudaGetSymbolAddress((void**)&pW1h, g_W1h);
    cudaGetSymbolAddress((void**)&pW2h, g_W2h);
    cudaGetSymbolAddress((void**)&pWph, g_Wph);

    conv_f2h(Wq, pWqh, NLAYERS * DM * DM);
    conv_f2h(Wk, pWkh, NLAYERS * DM * DM);
    conv_f2h(Wv, pWvh, NLAYERS * DM * DM);
    conv_f2h(Wo, pWoh, NLAYERS * DM * DM);
    conv_f2h(W1, pW1h, NLAYERS * DM * DFF);
    conv_f2h(W2, pW2h, NLAYERS * DFF * DM);
    conv_f2h(Wp, pWph, DM * NCLS);

    embed_kernel<<<(NTOK * DM) / 256, 256>>>(x, E, pH, pHh);

    const dim3 gDM(DM / 128, NTOK / 128);     // (4, 512)
    const dim3 gFF(DFF / 128, NTOK / 128);    // (16, 512)
    const dim3 gP(1, NTOK / 128);             // (1, 512)

    for (int l = 0; l < NLAYERS; l++) {
        const size_t wOff  = (size_t)l * DM * DM;
        const size_t bOff  = (size_t)l * DM;
        const size_t w1Off = (size_t)l * DM * DFF;
        const size_t b1Off = (size_t)l * DFF;
        const size_t w2Off = (size_t)l * DFF * DM;

        hgemm<1,1,0><<<gDM, 256>>>(pHh, pWqh + wOff, bq + bOff, pQ, (__half*)0, NTOK, DM, DM);
        hgemm<1,1,0><<<gDM, 256>>>(pHh, pWkh + wOff, bk + bOff, pK, (__half*)0, NTOK, DM, DM);
        hgemm<0,1,0><<<gDM, 256>>>(pHh, pWvh + wOff, bv + bOff, pV, (__half*)0, NTOK, DM, DM);

        scan_kernel<<<BB * NH, 64>>>(pQ, pK, pV, pAh);

        hgemm<0,1,0><<<gDM, 256>>>(pAh, pWoh + wOff, bo + bOff, pT, (__half*)0, NTOK, DM, DM);
        add_ln_kernel<<<NTOK, 128>>>(pH, pHh, pT, g1 + bOff, be1 + bOff);

        hgemm<2,0,1><<<gFF, 256>>>(pHh, pW1h + w1Off, b1 + b1Off, (float*)0, pFh, NTOK, DFF, DM);
        hgemm<0,1,0><<<gDM, 256>>>(pFh, pW2h + w2Off, b2 + bOff, pT, (__half*)0, NTOK, DM, DFF);
        add_ln_kernel<<<NTOK, 128>>>(pH, pHh, pT, g2 + bOff, be2 + bOff);
    }

    hgemm<0,1,0><<<gP, 256>>>(pHh, pWph, bp, pY, (__half*)0, NTOK, NCLS, DM);
    remap_kernel<<<(BB * TT * NCLS) / 256, 256>>>(pY, out);
}